// round 8
// baseline (speedup 1.0000x reference)
#include <cuda_runtime.h>

#define N 512
#define BATCH 256
#define CHUNKS 8                    // chunks per batch row
#define TPB 256
#define GRID (CHUNKS * BATCH)       // 2048 blocks
#define PF 4                        // prefetch depth (float4 per thread)

// Scratch (no device allocs allowed)
__device__ __align__(16) float g_u[N];
__device__ __align__(16) float g_v[N];
__device__ float g_partial2[BATCH][CHUNKS];
__device__ int g_proj_cnt = 0;      // proj blocks completed
__device__ int g_flag     = 0;      // u,v ready (release/acquire)
__device__ int g_done_cnt = 0;      // reduce blocks completed

__global__ void __launch_bounds__(TPB, 6)
fused_kernel(const float* __restrict__ x,
             const float* __restrict__ wh,
             const float* __restrict__ wv,
             const float* __restrict__ bias,
             float* __restrict__ out) {
    const int bid = blockIdx.x;
    const int t   = threadIdx.x;
    const int b   = bid >> 3;        // batch row
    const int c   = bid & (CHUNKS - 1);

    __shared__ float ru[TPB / 32], rv[TPB / 32];
    __shared__ bool  is_last;

    // ----------------------------------------------------------------------
    // Phase 1 (blocks 0..511): u[k] = sum_i wh[i]*cu(i)*cos((2k+1)i pi/2N),
    // same for v. cospif arg numerator (2k+1)*i < 2^24 -> exact fp32.
    // ----------------------------------------------------------------------
    if (bid < N) {
        const int k = bid;
        const float c0 = sqrtf(1.0f / N);
        const float c1 = sqrtf(2.0f / N);
        const float two_k_p1 = (float)(2 * k + 1);
        float su = 0.f, sv = 0.f;
        #pragma unroll
        for (int r = 0; r < N / TPB; ++r) {          // 2 iters
            int i = r * TPB + t;
            float cu = (i == 0) ? c0 : c1;
            float tt = two_k_p1 * (float)i * (1.0f / (2.0f * N));
            float cc = cospif(tt) * cu;
            su = fmaf(wh[i], cc, su);
            sv = fmaf(wv[i], cc, sv);
        }
        #pragma unroll
        for (int o = 16; o > 0; o >>= 1) {
            su += __shfl_down_sync(0xffffffffu, su, o);
            sv += __shfl_down_sync(0xffffffffu, sv, o);
        }
        if ((t & 31) == 0) { ru[t >> 5] = su; rv[t >> 5] = sv; }
        __syncthreads();
        if (t == 0) {
            float fu = 0.f, fv = 0.f;
            #pragma unroll
            for (int w = 0; w < TPB / 32; ++w) { fu += ru[w]; fv += rv[w]; }
            g_u[k] = fu;
            g_v[k] = fv;
            __threadfence();
            int old = atomicAdd(&g_proj_cnt, 1);
            if (old == N - 1) {
                __threadfence();
                *((volatile int*)&g_flag) = 1;       // release u,v
            }
        }
    }

    // ----------------------------------------------------------------------
    // Phase 2: prefetch x (independent of u,v) so DRAM stays busy during proj.
    // ----------------------------------------------------------------------
    const int f4_per_row   = (N * N) / 4;            // 65536
    const int f4_per_chunk = f4_per_row / CHUNKS;    // 8192
    const int iters        = f4_per_chunk / TPB;     // 32

    const float4* __restrict__ xr =
        reinterpret_cast<const float4*>(x) + (size_t)b * f4_per_row + c * f4_per_chunk;

    float4 buf[PF];
    #pragma unroll
    for (int p = 0; p < PF; ++p)
        buf[p] = __ldcs(&xr[p * TPB + t]);

    // Acquire u,v. launch_bounds(256,6) -> wave 1 has >=888 resident blocks,
    // so all 512 proj blocks are resident before any spinner must retire.
    if (t == 0) {
        while (*((volatile int*)&g_flag) == 0) __nanosleep(64);
    }
    __syncthreads();
    __threadfence();                                  // acquire fence

    // ----------------------------------------------------------------------
    // Phase 3: streaming weighted reduction.
    // Index structure: for f = i*TPB + t (float4 idx in chunk),
    //   v index (f&127)*4 = (t&127)*4  -> per-thread CONSTANT float4
    //   u index c*64 + 2i + (t>>7)     -> one broadcast scalar per iter
    // ----------------------------------------------------------------------
    const float4 v4 = *reinterpret_cast<const float4*>(&g_v[(t & 127) * 4]);
    const float* __restrict__ up = g_u + c * (N / CHUNKS) + (t >> 7);

    float acc0 = 0.f, acc1 = 0.f;
    #pragma unroll
    for (int p = 0; p < PF; ++p) {
        float4 xv = buf[p];
        float dot = fmaf(xv.x, v4.x, fmaf(xv.y, v4.y,
                    fmaf(xv.z, v4.z, xv.w * v4.w)));
        if (p & 1) acc1 = fmaf(up[2 * p], dot, acc1);
        else       acc0 = fmaf(up[2 * p], dot, acc0);
    }
    #pragma unroll 4
    for (int i = PF; i < iters; ++i) {
        float4 xv = __ldcs(&xr[i * TPB + t]);
        float dot = fmaf(xv.x, v4.x, fmaf(xv.y, v4.y,
                    fmaf(xv.z, v4.z, xv.w * v4.w)));
        if (i & 1) acc1 = fmaf(up[2 * i], dot, acc1);
        else       acc0 = fmaf(up[2 * i], dot, acc0);
    }
    float acc = acc0 + acc1;

    // deterministic block reduction
    __shared__ float red[TPB / 32];
    #pragma unroll
    for (int o = 16; o > 0; o >>= 1)
        acc += __shfl_down_sync(0xffffffffu, acc, o);
    if ((t & 31) == 0) red[t >> 5] = acc;
    __syncthreads();
    if (t == 0) {
        float s = 0.f;
        #pragma unroll
        for (int w = 0; w < TPB / 32; ++w) s += red[w];
        g_partial2[b][c] = s;
    }

    // ----------------------------------------------------------------------
    // Phase 4: last block finishes (sigmoid) and resets state for replay.
    // ----------------------------------------------------------------------
    __threadfence();
    if (t == 0) {
        int old = atomicAdd(&g_done_cnt, 1);
        is_last = (old == GRID - 1);
    }
    __syncthreads();
    if (is_last) {
        __threadfence();                              // see all partials
        if (t < BATCH) {
            float r = bias[0];
            #pragma unroll
            for (int cc = 0; cc < CHUNKS; ++cc) r += g_partial2[t][cc];
            out[t] = 1.0f / (1.0f + __expf(-r));
        }
        if (t == 0) {                                 // reset for next replay
            g_done_cnt = 0;
            g_proj_cnt = 0;
            g_flag     = 0;
        }
    }
}

extern "C" void kernel_launch(void* const* d_in, const int* in_sizes, int n_in,
                              void* d_out, int out_size) {
    const float* x    = (const float*)d_in[0];
    const float* wh   = (const float*)d_in[1];
    const float* wv   = (const float*)d_in[2];
    const float* bias = (const float*)d_in[3];
    float* out = (float*)d_out;

    fused_kernel<<<GRID, TPB>>>(x, wh, wv, bias, out);
}

// round 9
// speedup vs baseline: 1.0645x; 1.0645x over previous
#include <cuda_runtime.h>

#define N 512
#define BATCH 256
#define CHUNKS 8                    // chunks per batch row
#define TPB 256
#define GRID (CHUNKS * BATCH)       // 2048 blocks
#define PROJ_TPB 128

// Scratch (no device allocs allowed)
__device__ __align__(16) float g_u[N];
__device__ __align__(16) float g_v[N];
__device__ float g_partial2[BATCH][CHUNKS];
__device__ int g_done_cnt = 0;      // reduce blocks completed

// ---------------------------------------------------------------------------
// Kernel A (parallel): u[k] = sum_i wh[i]*cu(i)*cos((2k+1) i pi/(2N)),
// same for v. One block per k (512 blocks), 128 threads; deterministic tree.
// cospif arg: (2k+1)*i/1024, numerator < 2^24 -> exact in fp32.
// ---------------------------------------------------------------------------
__global__ void __launch_bounds__(PROJ_TPB)
proj_kernel(const float* __restrict__ wh, const float* __restrict__ wv) {
    const int k = blockIdx.x;
    const int t = threadIdx.x;

    const float c0 = sqrtf(1.0f / N);
    const float c1 = sqrtf(2.0f / N);
    const float two_k_p1 = (float)(2 * k + 1);

    float su = 0.f, sv = 0.f;
    #pragma unroll
    for (int r = 0; r < N / PROJ_TPB; ++r) {         // 4 iters
        int i = r * PROJ_TPB + t;
        float cu = (i == 0) ? c0 : c1;
        float tt = two_k_p1 * (float)i * (1.0f / (2.0f * N));
        float c = cospif(tt) * cu;
        su = fmaf(wh[i], c, su);
        sv = fmaf(wv[i], c, sv);
    }

    __shared__ float ru[PROJ_TPB / 32], rv[PROJ_TPB / 32];
    #pragma unroll
    for (int o = 16; o > 0; o >>= 1) {
        su += __shfl_down_sync(0xffffffffu, su, o);
        sv += __shfl_down_sync(0xffffffffu, sv, o);
    }
    if ((t & 31) == 0) { ru[t >> 5] = su; rv[t >> 5] = sv; }
    __syncthreads();
    if (t == 0) {
        g_u[k] = ru[0] + ru[1] + ru[2] + ru[3];
        g_v[k] = rv[0] + rv[1] + rv[2] + rv[3];
    }
}

// ---------------------------------------------------------------------------
// Kernel B: streaming weighted reduction + fused finish (last-block sigmoid).
// grid = 2048; block (b,c) handles 8192 float4 of row b, chunk c.
// Index structure for f = i*TPB + t:
//   v index (f&127)*4 = (t&127)*4 -> per-thread CONSTANT float4 (hoisted)
//   u index c*64 + 2i + (t>>7)    -> one broadcast scalar per iter (L1 hit)
// ---------------------------------------------------------------------------
__global__ void __launch_bounds__(TPB)
reduce_kernel(const float* __restrict__ x,
              const float* __restrict__ bias,
              float* __restrict__ out) {
    const int bid = blockIdx.x;
    const int t   = threadIdx.x;
    const int b   = bid >> 3;
    const int c   = bid & (CHUNKS - 1);

    const int f4_per_row   = (N * N) / 4;            // 65536
    const int f4_per_chunk = f4_per_row / CHUNKS;    // 8192
    const int iters        = f4_per_chunk / TPB;     // 32

    const float4* __restrict__ xr =
        reinterpret_cast<const float4*>(x) + (size_t)b * f4_per_row + c * f4_per_chunk;

    const float4 v4 = *reinterpret_cast<const float4*>(&g_v[(t & 127) * 4]);
    const float* __restrict__ up = g_u + c * (N / CHUNKS) + (t >> 7);

    float acc0 = 0.f, acc1 = 0.f;
    #pragma unroll 8
    for (int i = 0; i < iters; ++i) {
        float4 xv = xr[i * TPB + t];                 // plain LDG.128 (6.0 TB/s cfg)
        float dot = fmaf(xv.x, v4.x, fmaf(xv.y, v4.y,
                    fmaf(xv.z, v4.z, xv.w * v4.w)));
        if (i & 1) acc1 = fmaf(up[2 * i], dot, acc1);
        else       acc0 = fmaf(up[2 * i], dot, acc0);
    }
    float acc = acc0 + acc1;

    // deterministic block reduction
    __shared__ float red[TPB / 32];
    __shared__ bool  is_last;
    #pragma unroll
    for (int o = 16; o > 0; o >>= 1)
        acc += __shfl_down_sync(0xffffffffu, acc, o);
    if ((t & 31) == 0) red[t >> 5] = acc;
    __syncthreads();
    if (t == 0) {
        float s = 0.f;
        #pragma unroll
        for (int w = 0; w < TPB / 32; ++w) s += red[w];
        g_partial2[b][c] = s;
        __threadfence();
        int old = atomicAdd(&g_done_cnt, 1);
        is_last = (old == GRID - 1);
    }
    __syncthreads();

    // last block: sigmoid over all 256 batch entries, deterministic order
    if (is_last) {
        __threadfence();                             // see all partials
        float r = bias[0];
        #pragma unroll
        for (int cc = 0; cc < CHUNKS; ++cc) r += g_partial2[t][cc];
        out[t] = 1.0f / (1.0f + __expf(-r));
        if (t == 0) g_done_cnt = 0;                  // reset for graph replay
    }
}

extern "C" void kernel_launch(void* const* d_in, const int* in_sizes, int n_in,
                              void* d_out, int out_size) {
    const float* x    = (const float*)d_in[0];
    const float* wh   = (const float*)d_in[1];
    const float* wv   = (const float*)d_in[2];
    const float* bias = (const float*)d_in[3];
    float* out = (float*)d_out;

    proj_kernel<<<N, PROJ_TPB>>>(wh, wv);
    reduce_kernel<<<GRID, TPB>>>(x, bias, out);
}

// round 11
// speedup vs baseline: 1.0971x; 1.0306x over previous
#include <cuda_runtime.h>

#define N 512
#define BATCH 256
#define CHUNKS 8                    // chunks per batch row
#define TPB 256
#define GRID (CHUNKS * BATCH)       // 2048 blocks
#define PROJ_TPB 128

// Scratch (no device allocs allowed)
__device__ __align__(16) float g_u[N];
__device__ __align__(16) float g_v[N];
__device__ float g_partial2[BATCH][CHUNKS];
__device__ int g_done_cnt = 0;      // reduce blocks completed

// ---------------------------------------------------------------------------
// Kernel A (parallel): u[k] = sum_i wh[i]*cu(i)*cos((2k+1) i pi/(2N)),
// same for v. One block per k (512 blocks), 128 threads; deterministic tree.
// cospif arg: (2k+1)*i/1024, numerator < 2^24 -> exact in fp32.
// ---------------------------------------------------------------------------
__global__ void __launch_bounds__(PROJ_TPB)
proj_kernel(const float* __restrict__ wh, const float* __restrict__ wv) {
    const int k = blockIdx.x;
    const int t = threadIdx.x;

    const float c0 = sqrtf(1.0f / N);
    const float c1 = sqrtf(2.0f / N);
    const float two_k_p1 = (float)(2 * k + 1);

    float su = 0.f, sv = 0.f;
    #pragma unroll
    for (int r = 0; r < N / PROJ_TPB; ++r) {         // 4 iters
        int i = r * PROJ_TPB + t;
        float cu = (i == 0) ? c0 : c1;
        float tt = two_k_p1 * (float)i * (1.0f / (2.0f * N));
        float c = cospif(tt) * cu;
        su = fmaf(wh[i], c, su);
        sv = fmaf(wv[i], c, sv);
    }

    __shared__ float ru[PROJ_TPB / 32], rv[PROJ_TPB / 32];
    #pragma unroll
    for (int o = 16; o > 0; o >>= 1) {
        su += __shfl_down_sync(0xffffffffu, su, o);
        sv += __shfl_down_sync(0xffffffffu, sv, o);
    }
    if ((t & 31) == 0) { ru[t >> 5] = su; rv[t >> 5] = sv; }
    __syncthreads();
    if (t == 0) {
        g_u[k] = ru[0] + ru[1] + ru[2] + ru[3];
        g_v[k] = rv[0] + rv[1] + rv[2] + rv[3];
    }
}

// ---------------------------------------------------------------------------
// Kernel B: streaming weighted reduction + fused finish (last-block sigmoid).
// grid = 2048; block (b,c) handles 8192 float4 of row b, chunk c.
// Index structure for f = i*TPB + t:
//   v index (f&127)*4 = (t&127)*4 -> per-thread CONSTANT float4 (hoisted)
//   u index c*64 + 2i + (t>>7)    -> one broadcast scalar per iter (L1 hit)
// MLP: groups of 4 independent LDG.128 issued back-to-back before any
// consumer FMA (front-batched); launch_bounds(256,5) caps regs at 51 so the
// 4 float4 buffers fit without spilling while keeping 5 blocks/SM.
// ---------------------------------------------------------------------------
__global__ void __launch_bounds__(TPB, 5)
reduce_kernel(const float* __restrict__ x,
              const float* __restrict__ bias,
              float* __restrict__ out) {
    const int bid = blockIdx.x;
    const int t   = threadIdx.x;
    const int b   = bid >> 3;
    const int c   = bid & (CHUNKS - 1);

    const int f4_per_row   = (N * N) / 4;            // 65536
    const int f4_per_chunk = f4_per_row / CHUNKS;    // 8192
    const int iters        = f4_per_chunk / TPB;     // 32

    const float4* __restrict__ xr =
        reinterpret_cast<const float4*>(x) + (size_t)b * f4_per_row + c * f4_per_chunk;

    const float4 v4 = *reinterpret_cast<const float4*>(&g_v[(t & 127) * 4]);
    const float* __restrict__ up = g_u + c * (N / CHUNKS) + (t >> 7);

    float acc0 = 0.f, acc1 = 0.f;
    #pragma unroll
    for (int g = 0; g < iters; g += 4) {
        // 4 independent loads, addresses computed first, loads clustered.
        const float4* p0 = xr + (g + 0) * TPB + t;
        const float4* p1 = xr + (g + 1) * TPB + t;
        const float4* p2 = xr + (g + 2) * TPB + t;
        const float4* p3 = xr + (g + 3) * TPB + t;
        float4 x0 = __ldg(p0);
        float4 x1 = __ldg(p1);
        float4 x2 = __ldg(p2);
        float4 x3 = __ldg(p3);

        float d0 = fmaf(x0.x, v4.x, fmaf(x0.y, v4.y, fmaf(x0.z, v4.z, x0.w * v4.w)));
        float d1 = fmaf(x1.x, v4.x, fmaf(x1.y, v4.y, fmaf(x1.z, v4.z, x1.w * v4.w)));
        float d2 = fmaf(x2.x, v4.x, fmaf(x2.y, v4.y, fmaf(x2.z, v4.z, x2.w * v4.w)));
        float d3 = fmaf(x3.x, v4.x, fmaf(x3.y, v4.y, fmaf(x3.z, v4.z, x3.w * v4.w)));

        acc0 = fmaf(up[2 * (g + 0)], d0, acc0);
        acc1 = fmaf(up[2 * (g + 1)], d1, acc1);
        acc0 = fmaf(up[2 * (g + 2)], d2, acc0);
        acc1 = fmaf(up[2 * (g + 3)], d3, acc1);
    }
    float acc = acc0 + acc1;

    // deterministic block reduction
    __shared__ float red[TPB / 32];
    __shared__ bool  is_last;
    #pragma unroll
    for (int o = 16; o > 0; o >>= 1)
        acc += __shfl_down_sync(0xffffffffu, acc, o);
    if ((t & 31) == 0) red[t >> 5] = acc;
    __syncthreads();
    if (t == 0) {
        float s = 0.f;
        #pragma unroll
        for (int w = 0; w < TPB / 32; ++w) s += red[w];
        g_partial2[b][c] = s;
        __threadfence();
        int old = atomicAdd(&g_done_cnt, 1);
        is_last = (old == GRID - 1);
    }
    __syncthreads();

    // last block: sigmoid over all 256 batch entries, deterministic order
    if (is_last) {
        __threadfence();                             // see all partials
        float r = bias[0];
        #pragma unroll
        for (int cc = 0; cc < CHUNKS; ++cc) r += g_partial2[t][cc];
        out[t] = 1.0f / (1.0f + __expf(-r));
        if (t == 0) g_done_cnt = 0;                  // reset for graph replay
    }
}

extern "C" void kernel_launch(void* const* d_in, const int* in_sizes, int n_in,
                              void* d_out, int out_size) {
    const float* x    = (const float*)d_in[0];
    const float* wh   = (const float*)d_in[1];
    const float* wv   = (const float*)d_in[2];
    const float* bias = (const float*)d_in[3];
    float* out = (float*)d_out;

    proj_kernel<<<N, PROJ_TPB>>>(wh, wv);
    reduce_kernel<<<GRID, TPB>>>(x, bias, out);
}